// round 5
// baseline (speedup 1.0000x reference)
#include <cuda_runtime.h>

#define NB 8
#define NS 2048
#define NE 8
#define NH 2
#define ND 4
#define NT (NB*NS)        // 16384 tokens
#define NBH (NB*NH)       // 16 (batch, head) pairs
#define SPLITS 16
#define KPS (NS/SPLITS)   // 128 keys per split
#define NPAIR (KPS/2)     // 64 key pairs
#define QB 256            // queries per CTA (2 per thread)

// log2(e) / sqrt(D) folded into q so scores feed ex2 directly
#define QSCALE 0.72134752044448169f

// Scratch (device globals — no allocation allowed)
__device__ float4 g_pnum[NBH*SPLITS*NS];   // partial numerators
__device__ float  g_pden[NBH*SPLITS*NS];   // partial denominators

typedef unsigned long long ull;

// ---- packed f32x2 helpers ----
static __device__ __forceinline__ ull pack2(float a, float b) {
    ull r; asm("mov.b64 %0, {%1,%2};" : "=l"(r) : "f"(a), "f"(b)); return r;
}
static __device__ __forceinline__ void unpack2(ull v, float& a, float& b) {
    asm("mov.b64 {%0,%1}, %2;" : "=f"(a), "=f"(b) : "l"(v));
}
static __device__ __forceinline__ ull fma2p(ull a, ull b, ull c) {
    ull d; asm("fma.rn.f32x2 %0, %1, %2, %3;" : "=l"(d) : "l"(a), "l"(b), "l"(c)); return d;
}
static __device__ __forceinline__ ull mul2p(ull a, ull b) {
    ull d; asm("mul.rn.f32x2 %0, %1, %2;" : "=l"(d) : "l"(a), "l"(b)); return d;
}
static __device__ __forceinline__ float ex2f(float x) {
    float r; asm("ex2.approx.f32 %0, %1;" : "=f"(r) : "f"(x)); return r;
}
static __device__ __forceinline__ float rcpf(float x) {
    float r; asm("rcp.approx.f32 %0, %1;" : "=f"(r) : "f"(x)); return r;
}

// ============================================================
// Fused QKV + split-K softmax attention.
// grid = (NS/QB, SPLITS, NBH), 128 threads.
// K/V staged key-pair-packed (SoA, conflict-free).
// Each thread: 2 queries x 2 keys per inner iteration.
// ============================================================
__global__ void __launch_bounds__(128, 8) attn_kernel(const float* __restrict__ x,
                                                      const float* __restrict__ Wq,
                                                      const float* __restrict__ Wk,
                                                      const float* __restrict__ Wv) {
    __shared__ float sWq[32], sWk[32], sWv[32];   // this head's 4 rows (4x8)
    __shared__ ulonglong2 sK01[NPAIR];
    __shared__ ulonglong2 sK23[NPAIR];
    __shared__ ulonglong2 sV01[NPAIR];
    __shared__ ulonglong2 sV23[NPAIR];

    const int bh    = blockIdx.z;
    const int split = blockIdx.y;
    const int tid   = threadIdx.x;
    const int b     = bh >> 1;
    const int h     = bh & 1;

    if (tid < 32) {
        sWq[tid] = Wq[h*32 + tid];
        sWk[tid] = Wk[h*32 + tid];
        sWv[tid] = Wv[h*32 + tid];
    }
    __syncthreads();

    const float4* x4 = (const float4*)x;

    // ---- stage one key pair per thread (threads 0..NPAIR-1) ----
    if (tid < NPAIR) {
        int tokA = b*NS + split*KPS + 2*tid;
        float4 a0 = x4[tokA*2], a1 = x4[tokA*2+1];
        float4 b0 = x4[tokA*2+2], b1 = x4[tokA*2+3];
        float xra[8] = {a0.x,a0.y,a0.z,a0.w,a1.x,a1.y,a1.z,a1.w};
        float xrb[8] = {b0.x,b0.y,b0.z,b0.w,b1.x,b1.y,b1.z,b1.w};
        float kA[4], vA[4], kB[4], vB[4];
#pragma unroll
        for (int d = 0; d < 4; d++) {
            float ka = 0.f, va = 0.f, kb = 0.f, vb = 0.f;
#pragma unroll
            for (int e = 0; e < 8; e++) {
                float wk = sWk[d*8 + e], wv = sWv[d*8 + e];
                ka += xra[e] * wk;  va += xra[e] * wv;
                kb += xrb[e] * wk;  vb += xrb[e] * wv;
            }
            kA[d] = ka; vA[d] = va; kB[d] = kb; vB[d] = vb;
        }
        ulonglong2 t;
        t.x = pack2(kA[0], kB[0]); t.y = pack2(kA[1], kB[1]); sK01[tid] = t;
        t.x = pack2(kA[2], kB[2]); t.y = pack2(kA[3], kB[3]); sK23[tid] = t;
        t.x = pack2(vA[0], vB[0]); t.y = pack2(vA[1], vB[1]); sV01[tid] = t;
        t.x = pack2(vA[2], vB[2]); t.y = pack2(vA[3], vB[3]); sV23[tid] = t;
    }

    // ---- this thread's 2 queries (qa = qi, qb = qi+128), {q,q}-packed ----
    const int qi = blockIdx.x * QB + tid;
    ull qa[4], qb[4];
    {
        int ta = b*NS + qi, tb = ta + 128;
        float4 a0 = x4[ta*2], a1 = x4[ta*2+1];
        float4 b0 = x4[tb*2], b1 = x4[tb*2+1];
        float xra[8] = {a0.x,a0.y,a0.z,a0.w,a1.x,a1.y,a1.z,a1.w};
        float xrb[8] = {b0.x,b0.y,b0.z,b0.w,b1.x,b1.y,b1.z,b1.w};
#pragma unroll
        for (int d = 0; d < 4; d++) {
            float sa = 0.f, sb = 0.f;
#pragma unroll
            for (int e = 0; e < 8; e++) {
                float w = sWq[d*8 + e];
                sa += xra[e] * w;
                sb += xrb[e] * w;
            }
            qa[d] = pack2(sa * QSCALE, sa * QSCALE);
            qb[d] = pack2(sb * QSCALE, sb * QSCALE);
        }
    }
    __syncthreads();

    const ull ONE2 = pack2(1.f, 1.f);
    ull na0 = 0, na1 = 0, na2 = 0, na3 = 0;   // query a numerators (key-pair lanes)
    ull nb0 = 0, nb1 = 0, nb2 = 0, nb3 = 0;   // query b
    ull dap = 0, dbp = 0;                     // denominators (key-pair lanes)

#pragma unroll 4
    for (int j = 0; j < NPAIR; j++) {
        ulonglong2 kA = sK01[j];     // {k0 pair | k1 pair}
        ulonglong2 kB = sK23[j];     // {k2 pair | k3 pair}
        ull sa = mul2p(qa[0], kA.x);
        ull sb = mul2p(qb[0], kA.x);
        sa = fma2p(qa[1], kA.y, sa);
        sb = fma2p(qb[1], kA.y, sb);
        sa = fma2p(qa[2], kB.x, sa);
        sb = fma2p(qb[2], kB.x, sb);
        sa = fma2p(qa[3], kB.y, sa);  // {score_a(2j), score_a(2j+1)}
        sb = fma2p(qb[3], kB.y, sb);
        float s0, s1, s2, s3;
        unpack2(sa, s0, s1);
        unpack2(sb, s2, s3);
        ull wa = pack2(ex2f(s0), ex2f(s1));
        ull wb = pack2(ex2f(s2), ex2f(s3));
        ulonglong2 vA = sV01[j];
        ulonglong2 vB = sV23[j];
        na0 = fma2p(wa, vA.x, na0);
        na1 = fma2p(wa, vA.y, na1);
        na2 = fma2p(wa, vB.x, na2);
        na3 = fma2p(wa, vB.y, na3);
        nb0 = fma2p(wb, vA.x, nb0);
        nb1 = fma2p(wb, vA.y, nb1);
        nb2 = fma2p(wb, vB.x, nb2);
        nb3 = fma2p(wb, vB.y, nb3);
        dap = fma2p(wa, ONE2, dap);
        dbp = fma2p(wb, ONE2, dbp);
    }

    // horizontal reduce key-pair lanes
    float lo, hi, x0, x1, x2, x3, y0, y1, y2, y3, da, db;
    unpack2(na0, lo, hi); x0 = lo + hi;
    unpack2(na1, lo, hi); x1 = lo + hi;
    unpack2(na2, lo, hi); x2 = lo + hi;
    unpack2(na3, lo, hi); x3 = lo + hi;
    unpack2(nb0, lo, hi); y0 = lo + hi;
    unpack2(nb1, lo, hi); y1 = lo + hi;
    unpack2(nb2, lo, hi); y2 = lo + hi;
    unpack2(nb3, lo, hi); y3 = lo + hi;
    unpack2(dap, lo, hi); da = lo + hi;
    unpack2(dbp, lo, hi); db = lo + hi;

    int base = (bh*SPLITS + split)*NS + qi;
    g_pnum[base]       = make_float4(x0, x1, x2, x3);
    g_pden[base]       = da;
    g_pnum[base + 128] = make_float4(y0, y1, y2, y3);
    g_pden[base + 128] = db;
}

// ============================================================
// Split reduction + analytic quantum measurement + Wo.
// 8 threads per token: gid bits = [quarter(2) | head(1) | token].
// Each thread loads 4 of 16 split-partials; tree-reduce via
// shfl_xor(1), shfl_xor(2); head exchange via shfl_xor(4).
// z_w = prod_{u<=w} cos(o_u + o_{u&3}) (w>=1); z_0 = prod_{u=1..7}.
// ============================================================
__global__ void __launch_bounds__(128) quantum_kernel(const float* __restrict__ Wo,
                                                      float* __restrict__ out) {
    __shared__ float sWo[64];
    int tid = threadIdx.x;
    if (tid < 64) sWo[tid] = Wo[tid];
    __syncthreads();

    int gid = blockIdx.x * 128 + tid;     // 0 .. NT*NH*4-1
    int quarter = gid & 3;
    int h = (gid >> 2) & 1;
    int t = gid >> 3;
    int b = t / NS, s = t % NS;
    int bh = b*NH + h;

    float nx = 0.f, ny = 0.f, nz = 0.f, nw = 0.f, den = 0.f;
#pragma unroll
    for (int i = 0; i < 4; i++) {
        int sp = quarter*4 + i;
        int idx = (bh*SPLITS + sp)*NS + s;
        float4 nn = g_pnum[idx];
        nx += nn.x; ny += nn.y; nz += nn.z; nw += nn.w;
        den += g_pden[idx];
    }
    // tree-reduce over the 4 quarter-threads
#pragma unroll
    for (int m = 1; m <= 2; m <<= 1) {
        nx  += __shfl_xor_sync(0xFFFFFFFFu, nx,  m);
        ny  += __shfl_xor_sync(0xFFFFFFFFu, ny,  m);
        nz  += __shfl_xor_sync(0xFFFFFFFFu, nz,  m);
        nw  += __shfl_xor_sync(0xFFFFFFFFu, nw,  m);
        den += __shfl_xor_sync(0xFFFFFFFFu, den, m);
    }
    float r = rcpf(den);
    float o0 = nx*r, o1 = ny*r, o2 = nz*r, o3 = nw*r;   // this head's 4 dims

    // other head's o (exchange across head bit)
    float p0 = __shfl_xor_sync(0xFFFFFFFFu, o0, 4);
    float p1 = __shfl_xor_sync(0xFFFFFFFFu, o1, 4);
    float p2 = __shfl_xor_sync(0xFFFFFFFFu, o2, 4);
    float p3 = __shfl_xor_sync(0xFFFFFFFFu, o3, 4);

    // c_u for this thread's u = h*4+d: arg = o_u + o_{u&3}
    float a0 = o0 + (h ? p0 : o0);
    float a1 = o1 + (h ? p1 : o1);
    float a2 = o2 + (h ? p2 : o2);
    float a3 = o3 + (h ? p3 : o3);
    float c0 = __cosf(a0), c1 = __cosf(a1), c2 = __cosf(a2), c3 = __cosf(a3);

    // gather all 8 c's
    float q0 = __shfl_xor_sync(0xFFFFFFFFu, c0, 4);
    float q1 = __shfl_xor_sync(0xFFFFFFFFu, c1, 4);
    float q2 = __shfl_xor_sync(0xFFFFFFFFu, c2, 4);
    float q3 = __shfl_xor_sync(0xFFFFFFFFu, c3, 4);
    float gc[8];
    gc[0] = h ? q0 : c0;  gc[1] = h ? q1 : c1;
    gc[2] = h ? q2 : c2;  gc[3] = h ? q3 : c3;
    gc[4] = h ? c0 : q0;  gc[5] = h ? c1 : q1;
    gc[6] = h ? c2 : q2;  gc[7] = h ? c3 : q3;

    // z products
    float z[8];
    float tp = gc[1];
    z[1] = gc[0] * tp;
#pragma unroll
    for (int w = 2; w < 8; w++) { tp *= gc[w]; z[w] = gc[0] * tp; }
    z[0] = tp;

    // this thread's 4 output features f = h*4+i (quarter 0 writes)
    if (quarter == 0) {
        float rr[4];
#pragma unroll
        for (int i = 0; i < 4; i++) {
            float sacc = 0.f;
#pragma unroll
            for (int qq = 0; qq < 8; qq++) sacc += z[qq] * sWo[(h*4 + i)*8 + qq];
            rr[i] = sacc;
        }
        ((float4*)out)[t*2 + h] = make_float4(rr[0], rr[1], rr[2], rr[3]);
    }
}

// ============================================================
extern "C" void kernel_launch(void* const* d_in, const int* in_sizes, int n_in,
                              void* d_out, int out_size) {
    const float* x  = (const float*)d_in[0];
    const float* Wq = (const float*)d_in[1];
    const float* Wk = (const float*)d_in[2];
    const float* Wv = (const float*)d_in[3];
    const float* Wo = (const float*)d_in[4];
    float* out = (float*)d_out;

    attn_kernel<<<dim3(NS/QB, SPLITS, NBH), 128>>>(x, Wq, Wk, Wv);
    quantum_kernel<<<NT*NH*4/128, 128>>>(Wo, out);
}

// round 6
// speedup vs baseline: 1.0511x; 1.0511x over previous
#include <cuda_runtime.h>

#define NB 8
#define NS 2048
#define NE 8
#define NH 2
#define ND 4
#define NT (NB*NS)        // 16384 tokens
#define NBH (NB*NH)       // 16 (batch, head) pairs
#define SPLITS 8
#define KPS (NS/SPLITS)   // 256 keys per split
#define NPAIR (KPS/2)     // 128 key pairs
#define QB 256            // queries per CTA (2 per thread)

// log2(e) / sqrt(D) folded into q so scores feed ex2 directly
#define QSCALE 0.72134752044448169f

// Scratch (device globals — no allocation allowed)
__device__ float4 g_pnum[NBH*SPLITS*NS];   // partial numerators
__device__ float  g_pden[NBH*SPLITS*NS];   // partial denominators

typedef unsigned long long ull;

// ---- packed f32x2 helpers ----
static __device__ __forceinline__ ull pack2(float a, float b) {
    ull r; asm("mov.b64 %0, {%1,%2};" : "=l"(r) : "f"(a), "f"(b)); return r;
}
static __device__ __forceinline__ void unpack2(ull v, float& a, float& b) {
    asm("mov.b64 {%0,%1}, %2;" : "=f"(a), "=f"(b) : "l"(v));
}
static __device__ __forceinline__ ull fma2p(ull a, ull b, ull c) {
    ull d; asm("fma.rn.f32x2 %0, %1, %2, %3;" : "=l"(d) : "l"(a), "l"(b), "l"(c)); return d;
}
static __device__ __forceinline__ ull mul2p(ull a, ull b) {
    ull d; asm("mul.rn.f32x2 %0, %1, %2;" : "=l"(d) : "l"(a), "l"(b)); return d;
}
static __device__ __forceinline__ float ex2f(float x) {
    float r; asm("ex2.approx.f32 %0, %1;" : "=f"(r) : "f"(x)); return r;
}
static __device__ __forceinline__ float rcpf(float x) {
    float r; asm("rcp.approx.f32 %0, %1;" : "=f"(r) : "f"(x)); return r;
}

// ============================================================
// Fused QKV + split-K softmax attention (R4-proven config).
// grid = (NS/QB, SPLITS, NBH), 128 threads.
// K/V staged key-pair-packed (SoA, conflict-free).
// Each thread: 2 queries x 2 keys per inner iteration.
// ============================================================
__global__ void __launch_bounds__(128, 7) attn_kernel(const float* __restrict__ x,
                                                      const float* __restrict__ Wq,
                                                      const float* __restrict__ Wk,
                                                      const float* __restrict__ Wv) {
    __shared__ float sWq[32], sWk[32], sWv[32];   // this head's 4 rows (4x8)
    __shared__ ulonglong2 sK01[NPAIR];
    __shared__ ulonglong2 sK23[NPAIR];
    __shared__ ulonglong2 sV01[NPAIR];
    __shared__ ulonglong2 sV23[NPAIR];

    const int bh    = blockIdx.z;
    const int split = blockIdx.y;
    const int tid   = threadIdx.x;
    const int b     = bh >> 1;
    const int h     = bh & 1;

    if (tid < 32) {
        sWq[tid] = Wq[h*32 + tid];
        sWk[tid] = Wk[h*32 + tid];
        sWv[tid] = Wv[h*32 + tid];
    }
    __syncthreads();

    const float4* x4 = (const float4*)x;

    // ---- stage one key pair per thread (keys 2*tid, 2*tid+1) ----
    {
        int tokA = b*NS + split*KPS + 2*tid;
        float4 a0 = x4[tokA*2], a1 = x4[tokA*2+1];
        float4 b0 = x4[tokA*2+2], b1 = x4[tokA*2+3];
        float xra[8] = {a0.x,a0.y,a0.z,a0.w,a1.x,a1.y,a1.z,a1.w};
        float xrb[8] = {b0.x,b0.y,b0.z,b0.w,b1.x,b1.y,b1.z,b1.w};
        float kA[4], vA[4], kB[4], vB[4];
#pragma unroll
        for (int d = 0; d < 4; d++) {
            float ka = 0.f, va = 0.f, kb = 0.f, vb = 0.f;
#pragma unroll
            for (int e = 0; e < 8; e++) {
                float wk = sWk[d*8 + e], wv = sWv[d*8 + e];
                ka += xra[e] * wk;  va += xra[e] * wv;
                kb += xrb[e] * wk;  vb += xrb[e] * wv;
            }
            kA[d] = ka; vA[d] = va; kB[d] = kb; vB[d] = vb;
        }
        ulonglong2 t;
        t.x = pack2(kA[0], kB[0]); t.y = pack2(kA[1], kB[1]); sK01[tid] = t;
        t.x = pack2(kA[2], kB[2]); t.y = pack2(kA[3], kB[3]); sK23[tid] = t;
        t.x = pack2(vA[0], vB[0]); t.y = pack2(vA[1], vB[1]); sV01[tid] = t;
        t.x = pack2(vA[2], vB[2]); t.y = pack2(vA[3], vB[3]); sV23[tid] = t;
    }

    // ---- this thread's 2 queries (qa = qi, qb = qi+128), {q,q}-packed ----
    const int qi = blockIdx.x * QB + tid;
    ull qa[4], qb[4];
    {
        int ta = b*NS + qi, tb = ta + 128;
        float4 a0 = x4[ta*2], a1 = x4[ta*2+1];
        float4 b0 = x4[tb*2], b1 = x4[tb*2+1];
        float xra[8] = {a0.x,a0.y,a0.z,a0.w,a1.x,a1.y,a1.z,a1.w};
        float xrb[8] = {b0.x,b0.y,b0.z,b0.w,b1.x,b1.y,b1.z,b1.w};
#pragma unroll
        for (int d = 0; d < 4; d++) {
            float sa = 0.f, sb = 0.f;
#pragma unroll
            for (int e = 0; e < 8; e++) {
                float w = sWq[d*8 + e];
                sa += xra[e] * w;
                sb += xrb[e] * w;
            }
            qa[d] = pack2(sa * QSCALE, sa * QSCALE);
            qb[d] = pack2(sb * QSCALE, sb * QSCALE);
        }
    }
    __syncthreads();

    const ull ONE2 = pack2(1.f, 1.f);
    ull na0 = 0, na1 = 0, na2 = 0, na3 = 0;   // query a numerators (key-pair lanes)
    ull nb0 = 0, nb1 = 0, nb2 = 0, nb3 = 0;   // query b
    ull dap = 0, dbp = 0;                     // denominators (key-pair lanes)

#pragma unroll 8
    for (int j = 0; j < NPAIR; j++) {
        ulonglong2 kA = sK01[j];     // {k0 pair | k1 pair}
        ulonglong2 kB = sK23[j];     // {k2 pair | k3 pair}
        ull sa = mul2p(qa[0], kA.x);
        ull sb = mul2p(qb[0], kA.x);
        sa = fma2p(qa[1], kA.y, sa);
        sb = fma2p(qb[1], kA.y, sb);
        sa = fma2p(qa[2], kB.x, sa);
        sb = fma2p(qb[2], kB.x, sb);
        sa = fma2p(qa[3], kB.y, sa);  // {score_a(2j), score_a(2j+1)}
        sb = fma2p(qb[3], kB.y, sb);
        float s0, s1, s2, s3;
        unpack2(sa, s0, s1);
        unpack2(sb, s2, s3);
        ull wa = pack2(ex2f(s0), ex2f(s1));
        ull wb = pack2(ex2f(s2), ex2f(s3));
        ulonglong2 vA = sV01[j];
        ulonglong2 vB = sV23[j];
        na0 = fma2p(wa, vA.x, na0);
        na1 = fma2p(wa, vA.y, na1);
        na2 = fma2p(wa, vB.x, na2);
        na3 = fma2p(wa, vB.y, na3);
        nb0 = fma2p(wb, vA.x, nb0);
        nb1 = fma2p(wb, vA.y, nb1);
        nb2 = fma2p(wb, vB.x, nb2);
        nb3 = fma2p(wb, vB.y, nb3);
        dap = fma2p(wa, ONE2, dap);
        dbp = fma2p(wb, ONE2, dbp);
    }

    // horizontal reduce key-pair lanes
    float lo, hi, x0, x1, x2, x3, y0, y1, y2, y3, da, db;
    unpack2(na0, lo, hi); x0 = lo + hi;
    unpack2(na1, lo, hi); x1 = lo + hi;
    unpack2(na2, lo, hi); x2 = lo + hi;
    unpack2(na3, lo, hi); x3 = lo + hi;
    unpack2(nb0, lo, hi); y0 = lo + hi;
    unpack2(nb1, lo, hi); y1 = lo + hi;
    unpack2(nb2, lo, hi); y2 = lo + hi;
    unpack2(nb3, lo, hi); y3 = lo + hi;
    unpack2(dap, lo, hi); da = lo + hi;
    unpack2(dbp, lo, hi); db = lo + hi;

    int base = (bh*SPLITS + split)*NS + qi;
    g_pnum[base]       = make_float4(x0, x1, x2, x3);
    g_pden[base]       = da;
    g_pnum[base + 128] = make_float4(y0, y1, y2, y3);
    g_pden[base + 128] = db;
}

// ============================================================
// Split reduction + analytic quantum measurement + Wo.
// 8 threads per token: gid bits = [token | head(1) | half(2)].
// Each thread loads 2 of 8 split-partials (MLP up, traffic
// unchanged); tree-reduce shfl_xor(1),(2); head exch shfl_xor(4).
// z_w = prod_{u<=w} cos(o_u + o_{u&3}) (w>=1); z_0 = prod_{u=1..7}.
// ============================================================
__global__ void __launch_bounds__(256) quantum_kernel(const float* __restrict__ Wo,
                                                      float* __restrict__ out) {
    __shared__ float sWo[64];
    int tid = threadIdx.x;
    if (tid < 64) sWo[tid] = Wo[tid];
    __syncthreads();

    int gid = blockIdx.x * 256 + tid;   // 0 .. NT*NH*4-1
    int half = gid & 3;                 // which split pair
    int h = (gid >> 2) & 1;
    int t = gid >> 3;
    int b = t >> 11, s = t & (NS-1);
    int bh = b*NH + h;

    float nx = 0.f, ny = 0.f, nz = 0.f, nw = 0.f, den = 0.f;
#pragma unroll
    for (int i = 0; i < 2; i++) {
        int sp = half*2 + i;
        int idx = (bh*SPLITS + sp)*NS + s;
        float4 nn = g_pnum[idx];
        nx += nn.x; ny += nn.y; nz += nn.z; nw += nn.w;
        den += g_pden[idx];
    }
    // tree-reduce over the 4 half-threads
#pragma unroll
    for (int m = 1; m <= 2; m <<= 1) {
        nx  += __shfl_xor_sync(0xFFFFFFFFu, nx,  m);
        ny  += __shfl_xor_sync(0xFFFFFFFFu, ny,  m);
        nz  += __shfl_xor_sync(0xFFFFFFFFu, nz,  m);
        nw  += __shfl_xor_sync(0xFFFFFFFFu, nw,  m);
        den += __shfl_xor_sync(0xFFFFFFFFu, den, m);
    }
    float r = rcpf(den);
    float o0 = nx*r, o1 = ny*r, o2 = nz*r, o3 = nw*r;   // this head's 4 dims

    // other head's o (exchange across head bit)
    float p0 = __shfl_xor_sync(0xFFFFFFFFu, o0, 4);
    float p1 = __shfl_xor_sync(0xFFFFFFFFu, o1, 4);
    float p2 = __shfl_xor_sync(0xFFFFFFFFu, o2, 4);
    float p3 = __shfl_xor_sync(0xFFFFFFFFu, o3, 4);

    // c_u for this thread's u = h*4+d: arg = o_u + o_{u&3}
    float a0 = o0 + (h ? p0 : o0);
    float a1 = o1 + (h ? p1 : o1);
    float a2 = o2 + (h ? p2 : o2);
    float a3 = o3 + (h ? p3 : o3);
    float c0 = __cosf(a0), c1 = __cosf(a1), c2 = __cosf(a2), c3 = __cosf(a3);

    // gather all 8 c's
    float q0 = __shfl_xor_sync(0xFFFFFFFFu, c0, 4);
    float q1 = __shfl_xor_sync(0xFFFFFFFFu, c1, 4);
    float q2 = __shfl_xor_sync(0xFFFFFFFFu, c2, 4);
    float q3 = __shfl_xor_sync(0xFFFFFFFFu, c3, 4);
    float gc[8];
    gc[0] = h ? q0 : c0;  gc[1] = h ? q1 : c1;
    gc[2] = h ? q2 : c2;  gc[3] = h ? q3 : c3;
    gc[4] = h ? c0 : q0;  gc[5] = h ? c1 : q1;
    gc[6] = h ? c2 : q2;  gc[7] = h ? c3 : q3;

    // z products
    float z[8];
    float tp = gc[1];
    z[1] = gc[0] * tp;
#pragma unroll
    for (int w = 2; w < 8; w++) { tp *= gc[w]; z[w] = gc[0] * tp; }
    z[0] = tp;

    // this thread's 4 output features f = h*4+i (half 0 writes)
    if (half == 0) {
        float rr[4];
#pragma unroll
        for (int i = 0; i < 4; i++) {
            float sacc = 0.f;
#pragma unroll
            for (int qq = 0; qq < 8; qq++) sacc += z[qq] * sWo[(h*4 + i)*8 + qq];
            rr[i] = sacc;
        }
        ((float4*)out)[t*2 + h] = make_float4(rr[0], rr[1], rr[2], rr[3]);
    }
}

// ============================================================
extern "C" void kernel_launch(void* const* d_in, const int* in_sizes, int n_in,
                              void* d_out, int out_size) {
    const float* x  = (const float*)d_in[0];
    const float* Wq = (const float*)d_in[1];
    const float* Wk = (const float*)d_in[2];
    const float* Wv = (const float*)d_in[3];
    const float* Wo = (const float*)d_in[4];
    float* out = (float*)d_out;

    attn_kernel<<<dim3(NS/QB, SPLITS, NBH), 128>>>(x, Wq, Wk, Wv);
    quantum_kernel<<<NT*NH*4/256, 256>>>(Wo, out);
}